// round 16
// baseline (speedup 1.0000x reference)
#include <cuda_runtime.h>
#include <cstdint>

/*
 Top-K mask of zero-diagonal outer(p,p), N=8192, K=262144.
 TWO kernels:
  k_sel: 512 blocks x 256 thr, software grid barrier. ALL cross-phase global
         reads are __ldcg / writes __stcg (L2-coherent; L1 is NOT invalidated
         by fences -- that was R15's bug). After the distributed sort, each
         block keeps a 32KB shared copy of sorted p and searches shared.
         Phases: hist -> scan(block0; zero hist) -> scatter -> run-fix ->
         shared copy -> L1 edge counts -> bracket -> L2 edge counts ->
         bracket -> enum -> block0 exact K-th key + tie cut (+ zero scratch).
  k_out: fused 268MB float4 streaming-store pass (store-roofline bound).
*/

#define N      8192
#define KTOP   262144u
#define NBINS  16384
#define KSHIFT 18
#define TIECAP 4096
#define CAP    (1u<<20)
#define NBSEL  512

__device__ unsigned g_hist[NBINS];
__device__ unsigned g_off[NBINS];
__device__ float    g_sval[N];
__device__ int      g_sidx[N];
__device__ unsigned g_cnt1[256];
__device__ unsigned g_cnt2[256];
__device__ unsigned g_keys[CAP];
__device__ unsigned g_flats[CAP];
__device__ unsigned g_m;
__device__ float    g_thr;
__device__ unsigned g_cut;
__device__ unsigned g_barcnt;
__device__ volatile unsigned g_gen;

__device__ __forceinline__ unsigned fkey(float f) {
    unsigned u = __float_as_uint(f);
    return u ^ (((unsigned)((int)u >> 31)) | 0x80000000u);
}
__device__ __forceinline__ float unflip(unsigned k) {
    unsigned u = (k & 0x80000000u) ? (k ^ 0x80000000u) : ~k;
    return __uint_as_float(u);
}

/* software grid barrier (all NBSEL blocks co-resident) */
__device__ __forceinline__ void gbar() {
    __threadfence();
    __syncthreads();
    if (threadIdx.x == 0) {
        unsigned old = g_gen;
        if (atomicAdd(&g_barcnt, 1u) == NBSEL - 1u) {
            g_barcnt = 0u;
            __threadfence();
            g_gen = old + 1u;
        } else {
            while (g_gen == old) __nanosleep(64);
        }
    }
    __syncthreads();
}

/* boundary search on SHARED sorted array, range [0,N):
   v>0: pred(m)=(v*s[m]>=T) true for m<b ; count=b
   v<0: pred true for m>=b ; count=N-b */
__device__ __forceinline__ int bsb(float v, float T, const float* s) {
    int lo = 0, hi = N;
    if (v > 0.0f) {
        while (lo < hi) { int m = (lo + hi) >> 1; if (v * s[m] >= T) lo = m + 1; else hi = m; }
    } else {
        while (lo < hi) { int m = (lo + hi) >> 1; if (v * s[m] >= T) hi = m; else lo = m + 1; }
    }
    return lo;
}

/* count(>=T) over 16 rows (4-row lockstep x4) on shared array, atomicAdd out */
__device__ __forceinline__ void count_edge(float T, int chunk, unsigned* out_e,
                                           const float* s, unsigned* red) {
    const int tid = threadIdx.x;
    unsigned c = 0;
    #pragma unroll
    for (int g = 0; g < 4; g++) {
        int r0 = chunk * 4096 + g * 1024 + tid;
        float v0 = s[r0];
        float v1 = s[r0 + 256];
        float v2 = s[r0 + 512];
        float v3 = s[r0 + 768];
        int a0 = 0, b0 = N, a1 = 0, b1 = N, a2 = 0, b2 = N, a3 = 0, b3 = N;
        #pragma unroll
        for (int st = 0; st < 14; st++) {  /* 14 guarded steps for range 8192 */
            if (a0 < b0) { int m = (a0 + b0) >> 1; bool pr = (v0 * s[m] >= T);
                           if ((v0 > 0.0f) ? pr : !pr) a0 = m + 1; else b0 = m; }
            if (a1 < b1) { int m = (a1 + b1) >> 1; bool pr = (v1 * s[m] >= T);
                           if ((v1 > 0.0f) ? pr : !pr) a1 = m + 1; else b1 = m; }
            if (a2 < b2) { int m = (a2 + b2) >> 1; bool pr = (v2 * s[m] >= T);
                           if ((v2 > 0.0f) ? pr : !pr) a2 = m + 1; else b2 = m; }
            if (a3 < b3) { int m = (a3 + b3) >> 1; bool pr = (v3 * s[m] >= T);
                           if ((v3 > 0.0f) ? pr : !pr) a3 = m + 1; else b3 = m; }
        }
        if (v0 != 0.0f) { unsigned cj = (v0 > 0.0f) ? (unsigned)a0 : (unsigned)(N - a0); if (v0 * v0 >= T) cj--; c += cj; }
        if (v1 != 0.0f) { unsigned cj = (v1 > 0.0f) ? (unsigned)a1 : (unsigned)(N - a1); if (v1 * v1 >= T) cj--; c += cj; }
        if (v2 != 0.0f) { unsigned cj = (v2 > 0.0f) ? (unsigned)a2 : (unsigned)(N - a2); if (v2 * v2 >= T) cj--; c += cj; }
        if (v3 != 0.0f) { unsigned cj = (v3 > 0.0f) ? (unsigned)a3 : (unsigned)(N - a3); if (v3 * v3 >= T) cj--; c += cj; }
    }
    #pragma unroll
    for (int d = 16; d > 0; d >>= 1) c += __shfl_down_sync(0xffffffffu, c, d);
    if ((tid & 31) == 0) red[tid >> 5] = c;
    __syncthreads();
    if (tid == 0) {
        unsigned ssum = 0;
        #pragma unroll
        for (int i = 0; i < 8; i++) ssum += red[i];
        atomicAdd(out_e, ssum);
    }
    __syncthreads();
}

__global__ void __launch_bounds__(256, 4) k_sel(const float* __restrict__ p) {
    extern __shared__ unsigned char smraw[];
    float*    s_val = (float*)smraw;               /* [8192] 32KB */
    unsigned* s_tie = (unsigned*)smraw;            /* alias; used only in P8 */
    __shared__ unsigned cur[256];
    __shared__ unsigned red[8];
    __shared__ unsigned hA[256], hB[256];
    __shared__ unsigned sh_t, s_ntie, s_binA, s_above, s_Tk, s_r, s_cut;

    const int tid = threadIdx.x;
    const int bid = blockIdx.x;
    const int gt  = bid * 256 + tid;     /* row id for bid < 32 */
    const unsigned e  = (unsigned)(bid >> 1);
    const int     chk = bid & 1;

    /* ---- P1: hist ---- */
    if (bid < 32) atomicAdd(&g_hist[fkey(__ldcg(&p[gt])) >> KSHIFT], 1u);
    gbar();

    /* ---- P2: scan by block 0 (suffix counts); zero hist for next replay ---- */
    if (bid == 0) {
        const int base = tid * 64;
        unsigned ct = 0;
        for (int j = 0; j < 64; j++) ct += __ldcg(&g_hist[base + j]);
        cur[tid] = ct; __syncthreads();
        for (int d = 1; d < 256; d <<= 1) {
            unsigned v2 = cur[tid] + ((tid + d < 256) ? cur[tid + d] : 0u);
            __syncthreads(); cur[tid] = v2; __syncthreads();
        }
        unsigned g = cur[tid] - ct;
        for (int j = 63; j >= 0; j--) {
            unsigned h = __ldcg(&g_hist[base + j]);
            __stcg(&g_off[base + j], g);
            g += h;
            __stcg(&g_hist[base + j], 0u);
        }
    }
    gbar();

    /* ---- P3: scatter (cursor atomics are L2-side) ---- */
    if (bid < 32) {
        float v = __ldcg(&p[gt]);
        unsigned b = fkey(v) >> KSHIFT;
        unsigned pos = atomicAdd(&g_off[b], 1u);
        __stcg(&g_sval[pos], v);
        g_sidx[pos] = gt;                /* consumed only via __ldcg later */
    }
    gbar();

    /* ---- P4: per-run insertion fix (runs disjoint per thread; ldcg/stcg) ---- */
    if (bid < 32) {
        int i = gt;
        unsigned bi = fkey(__ldcg(&g_sval[i])) >> KSHIFT;
        bool start = (i == 0) || ((fkey(__ldcg(&g_sval[i - 1])) >> KSHIFT) != bi);
        if (start) {
            int ee = i + 1;
            while (ee < N && (fkey(__ldcg(&g_sval[ee])) >> KSHIFT) == bi) ee++;
            for (int a = i + 1; a < ee; a++) {
                float kv = __ldcg(&g_sval[a]); int ki = __ldcg(&g_sidx[a]);
                int j = a - 1;
                while (j >= i && __ldcg(&g_sval[j]) < kv) {
                    __stcg(&g_sval[j + 1], __ldcg(&g_sval[j]));
                    g_sidx[j + 1] = __ldcg(&g_sidx[j]);
                    j--;
                }
                __stcg(&g_sval[j + 1], kv);
                g_sidx[j + 1] = ki;
            }
        }
    }
    gbar();

    /* ---- per-block shared copy of sorted values (L2-coherent reads) ---- */
    for (int i = tid; i < N; i += 256) s_val[i] = __ldcg(&g_sval[i]);
    __syncthreads();

    /* ---- P5: level-1 edge counts (shared searches) ---- */
    count_edge(unflip(0x80000000u + e * 0x800000u), chk, &g_cnt1[e], s_val, red);
    gbar();

    /* ---- derive bracket 1 ---- */
    if (tid == 0) sh_t = 0u;
    __syncthreads();
    if (__ldcg(&g_cnt1[tid]) >= KTOP) atomicMax(&sh_t, (unsigned)tid);
    __syncthreads();
    unsigned t1 = sh_t;
    unsigned lo1 = 0x80000000u + t1 * 0x800000u;
    unsigned hi1, chi1;
    if (t1 < 255u) { hi1 = lo1 + 0x800000u; chi1 = __ldcg(&g_cnt1[t1 + 1u]); }
    else           { hi1 = 0xFFFFFFFFu; chi1 = 0u; }
    unsigned stride2 = (hi1 - lo1) >> 8; if (!stride2) stride2 = 1u;
    __syncthreads();

    /* ---- P6: level-2 edge counts ---- */
    count_edge(unflip(lo1 + e * stride2), chk, &g_cnt2[e], s_val, red);
    gbar();

    /* ---- derive bracket 2 ---- */
    if (tid == 0) sh_t = 0u;
    __syncthreads();
    if (__ldcg(&g_cnt2[tid]) >= KTOP) atomicMax(&sh_t, (unsigned)tid);
    __syncthreads();
    unsigned t2 = sh_t;
    unsigned lo2 = lo1 + t2 * stride2;
    unsigned hi2, chi2;
    if (t2 < 255u) { hi2 = lo1 + (t2 + 1u) * stride2; chi2 = __ldcg(&g_cnt2[t2 + 1u]); }
    else           { hi2 = hi1; chi2 = chi1; }
    __syncthreads();

    /* ---- P7: enum candidates with key in [lo2, hi2) (blocks 0..31) ---- */
    if (bid < 32) {
        float v = s_val[gt];
        if (v != 0.0f) {
            int bA = bsb(v, unflip(lo2), s_val);
            int bB = bsb(v, unflip(hi2), s_val);
            int m0, m1;
            if (v > 0.0f) { m0 = bB; m1 = bA; } else { m0 = bA; m1 = bB; }
            if (m1 > m0) {
                unsigned fb = ((unsigned)__ldcg(&g_sidx[gt])) << 13;
                for (int m = m0; m < m1; m++) {
                    if (m == gt) continue;
                    unsigned pos = atomicAdd(&g_m, 1u);
                    if (pos < CAP) {
                        __stcg(&g_keys[pos],  fkey(v * s_val[m]));
                        __stcg(&g_flats[pos], fb + (unsigned)__ldcg(&g_sidx[m]));
                    }
                }
            }
        }
    }
    gbar();

    /* ---- P8: block 0 exact select + tie cut; zero scratch for next replay ---- */
    if (bid != 0) return;
    {
        const unsigned M = min(atomicAdd(&g_m, 0u), CAP);
        const unsigned w = hi2 - lo2;
        const unsigned binw = (w + 255u) >> 8;

        hA[tid] = 0u; hB[tid] = 0u;
        if (tid == 0) s_ntie = 0u;
        __syncthreads();

        for (unsigned i = tid; i < M; i += 256)
            atomicAdd(&hA[(__ldcg(&g_keys[i]) - lo2) / binw], 1u);
        __syncthreads();

        if (tid == 0) {
            unsigned acc = chi2;
            int bA = 0;
            for (int b = 255; b >= 0; b--) {
                if (acc + hA[b] >= KTOP) { bA = b; break; }
                acc += hA[b];
            }
            s_binA = (unsigned)bA; s_above = acc;
        }
        __syncthreads();
        const unsigned binA = s_binA;
        const unsigned base = lo2 + binA * binw;

        for (unsigned i = tid; i < M; i += 256) {
            unsigned k = __ldcg(&g_keys[i]);
            if ((k - lo2) / binw == binA) atomicAdd(&hB[k - base], 1u);
        }
        __syncthreads();

        if (tid == 0) {
            unsigned acc = s_above;
            unsigned off = 0;
            for (int o = (int)binw - 1; o >= 0; o--) {
                if (acc + hB[o] >= KTOP) { off = (unsigned)o; break; }
                acc += hB[o];
            }
            s_Tk = base + off;
            s_r = KTOP - acc;
        }
        __syncthreads();
        const unsigned Tk = s_Tk, r = s_r;

        for (unsigned i = tid; i < M; i += 256) {
            if (__ldcg(&g_keys[i]) == Tk) {
                unsigned pos = atomicAdd(&s_ntie, 1u);
                if (pos < TIECAP) s_tie[pos] = __ldcg(&g_flats[i]);
            }
        }
        __syncthreads();

        unsigned nt = min(s_ntie, (unsigned)TIECAP);
        if (tid == 0) s_cut = (r >= nt) ? 0xFFFFFFFFu : 0u;
        __syncthreads();
        if (r < nt) {
            for (unsigned i = tid; i < nt; i += 256) {
                unsigned x = s_tie[i];
                unsigned rk = 0;
                for (unsigned j = 0; j < nt; j++) rk += (s_tie[j] < x) ? 1u : 0u;
                if (rk == r) s_cut = x;
            }
        }
        __syncthreads();
        __stcg(&g_cnt1[tid], 0u);
        __stcg(&g_cnt2[tid], 0u);
        if (tid == 0) { __stcg(&g_m, 0u); g_thr = unflip(Tk); g_cut = s_cut; }
    }
}

/* ================= fused output pass (validated, roofline) ================ */
__device__ __forceinline__ float edgev(float v, float thr, unsigned flat, unsigned cut, bool diag) {
    bool ok = ((v > thr) | ((v == thr) & (flat < cut))) & (!diag);
    return ok ? 1.0f : 0.0f;
}

__global__ void k_out(const float* __restrict__ p, float4* __restrict__ out) {
    int row = blockIdx.y;
    float pi = __ldg(p + row);
    float thr = g_thr;
    unsigned cut = g_cut;
    const float4* __restrict__ q4 = (const float4*)p;
    int f0 = blockIdx.x * 1024 + threadIdx.x;
    unsigned fbase = ((unsigned)row) << 13;
    unsigned outrow = ((unsigned)row) << 11;
    #pragma unroll
    for (int k = 0; k < 4; k++) {
        int f = f0 + k * 256;
        float4 q = __ldg(q4 + f);
        unsigned j0 = ((unsigned)f) << 2;
        float4 o;
        o.x = edgev(pi * q.x, thr, fbase + j0 + 0u, cut, (j0 + 0u) == (unsigned)row);
        o.y = edgev(pi * q.y, thr, fbase + j0 + 1u, cut, (j0 + 1u) == (unsigned)row);
        o.z = edgev(pi * q.z, thr, fbase + j0 + 2u, cut, (j0 + 2u) == (unsigned)row);
        o.w = edgev(pi * q.w, thr, fbase + j0 + 3u, cut, (j0 + 3u) == (unsigned)row);
        __stcs(out + outrow + (unsigned)f, o);
    }
}

extern "C" void kernel_launch(void* const* d_in, const int* in_sizes, int n_in,
                              void* d_out, int out_size) {
    const float* p = (const float*)d_in[0];
    float* out = (float*)d_out;
    (void)in_sizes; (void)n_in; (void)out_size;

    k_sel<<<NBSEL, 256, 32768>>>(p);

    dim3 grid(2, N);
    k_out<<<grid, 256>>>(p, (float4*)out);
}